// round 1
// baseline (speedup 1.0000x reference)
#include <cuda_runtime.h>
#include <math.h>

#define BQ 2
#define TQ 2048
#define CQ 1024
#define HQ 16
#define DQ 64
#define BH (BQ*HQ)
#define M_ROWS (BQ*TQ)          // 4096

// Scratch (allocation-free rule: static device globals)
__device__ float g_q[BQ*HQ*TQ*DQ];
__device__ float g_k[BQ*HQ*TQ*DQ];
__device__ float g_v[BQ*HQ*TQ*DQ];
__device__ float g_y[BQ*TQ*CQ];

// ---------------------------------------------------------------------------
// SGEMM: C[M,N] = A[M,K] @ B[K,N] + bias[N]
// 64x64 tile, BK=16, 256 threads, 4x4 per thread.
// MODE 1: A = x, scatter outputs into g_q/g_k/g_v laid out [B,H,T,D]
// MODE 2: A = g_y (ignore A param), plain write to C
// ---------------------------------------------------------------------------
template<int MODE>
__global__ __launch_bounds__(256)
void sgemm64(const float* __restrict__ A, const float* __restrict__ B,
             const float* __restrict__ bias, float* __restrict__ C,
             int M, int N, int K)
{
    __shared__ float As[16][64];   // As[k][m]
    __shared__ float Bs[16][64];   // Bs[k][n]

    const float* Ap = (MODE == 2) ? (const float*)g_y : A;

    int tid = threadIdx.x;
    int tx = tid & 15;          // col group
    int ty = tid >> 4;          // row group
    int m0 = blockIdx.y * 64;
    int n0 = blockIdx.x * 64;

    float acc[4][4] = {};

    int arow  = tid >> 2;             // 0..63
    int acol4 = (tid & 3) * 4;        // 0..12
    int brow  = tid >> 4;             // 0..15
    int bcol4 = (tid & 15) * 4;       // 0..60

    const float* Aptr = Ap + (long)(m0 + arow) * K + acol4;
    const float* Bptr = B + (long)brow * N + n0 + bcol4;

    for (int k0 = 0; k0 < K; k0 += 16) {
        float4 a4 = *(const float4*)(Aptr + k0);
        float4 b4 = *(const float4*)(Bptr + (long)k0 * N);
        As[acol4 + 0][arow] = a4.x;
        As[acol4 + 1][arow] = a4.y;
        As[acol4 + 2][arow] = a4.z;
        As[acol4 + 3][arow] = a4.w;
        *(float4*)&Bs[brow][bcol4] = b4;
        __syncthreads();
        #pragma unroll
        for (int k = 0; k < 16; k++) {
            float4 av = *(const float4*)&As[k][ty * 4];
            float4 bv = *(const float4*)&Bs[k][tx * 4];
            float am[4] = {av.x, av.y, av.z, av.w};
            float bm[4] = {bv.x, bv.y, bv.z, bv.w};
            #pragma unroll
            for (int i = 0; i < 4; i++)
                #pragma unroll
                for (int j = 0; j < 4; j++)
                    acc[i][j] = fmaf(am[i], bm[j], acc[i][j]);
        }
        __syncthreads();
    }

    #pragma unroll
    for (int i = 0; i < 4; i++) {
        int m = m0 + ty * 4 + i;
        #pragma unroll
        for (int j = 0; j < 4; j++) {
            int n = n0 + tx * 4 + j;
            float v = acc[i][j] + bias[n];
            if (MODE == 1) {
                int which = n >> 10;        // 0=q 1=k 2=v
                int cc = n & 1023;
                int h = cc >> 6;
                int d = cc & 63;
                int b = m >> 11;            // T = 2048
                int t = m & 2047;
                float* dst = (which == 0) ? g_q : ((which == 1) ? g_k : g_v);
                dst[(((b << 4) + h) * (long)TQ + t) * DQ + d] = v;
            } else {
                C[(long)m * N + n] = v;
            }
        }
    }
}

// ---------------------------------------------------------------------------
// RoPE in-place on g_q, g_k. One thread per (bh,t) row per dim-pair.
// ---------------------------------------------------------------------------
__global__ void rope_kernel()
{
    int idx = blockIdx.x * blockDim.x + threadIdx.x;
    int lane = idx & 31;            // dim pair index j (dims j and j+32)
    int row = idx >> 5;             // bh*T + t
    if (row >= BH * TQ) return;
    int t = row & (TQ - 1);

    float inv_freq = 1.0f / powf(10000.0f, (float)(2 * lane) / 64.0f);
    float ang = (float)t * inv_freq;
    float c = cosf(ang);
    float s = sinf(ang);

    float* qp = g_q + (long)row * DQ;
    float q0 = qp[lane], q1 = qp[lane + 32];
    qp[lane]      = q0 * c - q1 * s;
    qp[lane + 32] = q1 * c + q0 * s;

    float* kp = g_k + (long)row * DQ;
    float k0 = kp[lane], k1 = kp[lane + 32];
    kp[lane]      = k0 * c - k1 * s;
    kp[lane + 32] = k1 * c + k0 * s;
}

// ---------------------------------------------------------------------------
// Flash attention fp32. grid = (BH, T/32). 256 threads = 8 warps.
// Each warp owns 4 query rows; block iterates 32-key chunks (causal).
// Output y laid out [B, T, H*D] (= [4096, 1024]) for the proj GEMM.
// ---------------------------------------------------------------------------
__global__ __launch_bounds__(256)
void flash_attn()
{
    __shared__ float Qs[32][64];     // broadcast reads only
    __shared__ float Ks[32][68];     // padded, float4-aligned rows
    __shared__ float Vs[32][68];
    __shared__ float Ps[8][4][33];   // per-warp probs for PV stage

    int bh = blockIdx.x;
    int r0 = blockIdx.y * 32;
    int tid = threadIdx.x;
    int w = tid >> 5;
    int lane = tid & 31;
    int row_in = w * 4;              // this warp's rows: r0+row_in .. +3

    const float* qb = g_q + (long)bh * TQ * DQ;
    const float* kb = g_k + (long)bh * TQ * DQ;
    const float* vb = g_v + (long)bh * TQ * DQ;

    // load Q tile
    for (int i = tid; i < 32 * 64; i += 256)
        Qs[i >> 6][i & 63] = qb[(long)(r0 + (i >> 6)) * DQ + (i & 63)];

    float mx[4], l[4], acc0[4], acc1[4];
    #pragma unroll
    for (int i = 0; i < 4; i++) { mx[i] = -1e30f; l[i] = 0.f; acc0[i] = 0.f; acc1[i] = 0.f; }

    int nch = blockIdx.y + 1;
    for (int c2 = 0; c2 < nch; c2++) {
        int kb0 = c2 * 32;
        __syncthreads();
        for (int i = tid; i < 32 * 64; i += 256) {
            int r = i >> 6, d = i & 63;
            Ks[r][d] = kb[(long)(kb0 + r) * DQ + d];
            Vs[r][d] = vb[(long)(kb0 + r) * DQ + d];
        }
        __syncthreads();

        // scores: lane handles key kb0+lane, 4 rows
        float s[4] = {0.f, 0.f, 0.f, 0.f};
        #pragma unroll
        for (int d4 = 0; d4 < 16; d4++) {
            float4 kv = *(const float4*)&Ks[lane][d4 * 4];
            #pragma unroll
            for (int i = 0; i < 4; i++) {
                float4 qv = *(const float4*)&Qs[row_in + i][d4 * 4];
                s[i] += qv.x * kv.x + qv.y * kv.y + qv.z * kv.z + qv.w * kv.w;
            }
        }

        __syncwarp();
        #pragma unroll
        for (int i = 0; i < 4; i++) {
            int row = r0 + row_in + i;
            float sv = (kb0 + lane > row) ? -1e30f : s[i] * 0.125f;
            float m2 = sv;
            #pragma unroll
            for (int off = 16; off; off >>= 1)
                m2 = fmaxf(m2, __shfl_xor_sync(0xffffffffu, m2, off));
            float mnew = fmaxf(mx[i], m2);
            float scale = __expf(mx[i] - mnew);
            float p = __expf(sv - mnew);
            float ps = p;
            #pragma unroll
            for (int off = 16; off; off >>= 1)
                ps += __shfl_xor_sync(0xffffffffu, ps, off);
            l[i] = l[i] * scale + ps;
            acc0[i] *= scale;
            acc1[i] *= scale;
            mx[i] = mnew;
            Ps[w][i][lane] = p;
        }
        __syncwarp();

        // PV: O[i][d] += sum_j P[i][j] * V[j][d], d = lane / lane+32
        #pragma unroll
        for (int j = 0; j < 32; j++) {
            float v0 = Vs[j][lane];
            float v1 = Vs[j][lane + 32];
            #pragma unroll
            for (int i = 0; i < 4; i++) {
                float pj = Ps[w][i][j];
                acc0[i] = fmaf(pj, v0, acc0[i]);
                acc1[i] = fmaf(pj, v1, acc1[i]);
            }
        }
        __syncwarp();
    }

    int b = bh >> 4, h = bh & 15;
    #pragma unroll
    for (int i = 0; i < 4; i++) {
        int t = r0 + row_in + i;
        float inv = 1.0f / l[i];
        float* yp = g_y + ((long)(b * TQ + t) * CQ) + h * 64;
        yp[lane]      = acc0[i] * inv;
        yp[lane + 32] = acc1[i] * inv;
    }
}

// ---------------------------------------------------------------------------
extern "C" void kernel_launch(void* const* d_in, const int* in_sizes, int n_in,
                              void* d_out, int out_size)
{
    const float* x     = (const float*)d_in[0];
    const float* Wqkv  = (const float*)d_in[1];
    const float* bqkv  = (const float*)d_in[2];
    const float* Wproj = (const float*)d_in[3];
    const float* bproj = (const float*)d_in[4];
    float* out = (float*)d_out;

    dim3 blk(256);
    // QKV GEMM + scatter to [B,H,T,D]
    sgemm64<1><<<dim3(3072 / 64, M_ROWS / 64), blk>>>(x, Wqkv, bqkv, nullptr,
                                                      M_ROWS, 3 * CQ, CQ);
    // RoPE on q,k
    rope_kernel<<<(BH * TQ * 32) / 256, 256>>>();
    // causal flash attention -> g_y [B,T,C]
    flash_attn<<<dim3(BH, TQ / 32), blk>>>();
    // output projection
    sgemm64<2><<<dim3(CQ / 64, M_ROWS / 64), blk>>>(nullptr, Wproj, bproj, out,
                                                    M_ROWS, CQ, CQ);
}

// round 4
// speedup vs baseline: 1.4255x; 1.4255x over previous
#include <cuda_runtime.h>
#include <cuda_bf16.h>
#include <stdint.h>
#include <math.h>

#define BQ 2
#define TQ 2048
#define CQ 1024
#define HQ 16
#define DQ 64
#define BH (BQ*HQ)
#define M_ROWS (BQ*TQ)          // 4096
#define K3 3072                 // tripled K for hi/lo split GEMM

// Scratch (allocation-free rule: static device globals)
__device__ float g_q[BQ*HQ*TQ*DQ];
__device__ float g_k[BQ*HQ*TQ*DQ];
__device__ float g_v[BQ*HQ*TQ*DQ];
__device__ float g_y[BQ*TQ*CQ];
__device__ __nv_bfloat16 g_A3[(long)M_ROWS * K3];     // [4096, 3072]
__device__ __nv_bfloat16 g_B3[(long)K3 * 3072];       // qkv weights split [3072, 3072]
__device__ __nv_bfloat16 g_B3p[(long)K3 * 1024];      // proj weights split [3072, 1024]

// ---------------------------------------------------------------------------
// fp32 -> (hi, lo) bf16 split conversions.
// A3 rows: [ah(0:1024) | ah(1024:2048) | al(2048:3072)]
// B3 rows: [bh ; bl ; bh] along K'
// SRC_Y=0: read from x param; SRC_Y=1: read from g_y
// ---------------------------------------------------------------------------
template<int SRC_Y>
__global__ void conv_A3(const float* __restrict__ src)
{
    int i = blockIdx.x * blockDim.x + threadIdx.x;
    if (i >= M_ROWS * CQ) return;
    const float* s = SRC_Y ? (const float*)g_y : src;
    int m = i >> 10, k = i & 1023;
    float v = s[i];
    __nv_bfloat16 hi = __float2bfloat16(v);
    __nv_bfloat16 lo = __float2bfloat16(v - __bfloat162float(hi));
    long base = (long)m * K3;
    g_A3[base + k] = hi;
    g_A3[base + 1024 + k] = hi;
    g_A3[base + 2048 + k] = lo;
}

// WHICH=0 -> g_B3 (N=3072), WHICH=1 -> g_B3p (N=1024)
template<int WHICH>
__global__ void conv_B3(const float* __restrict__ W)
{
    const int N = WHICH ? 1024 : 3072;
    __nv_bfloat16* dst = WHICH ? g_B3p : g_B3;
    int i = blockIdx.x * blockDim.x + threadIdx.x;
    if (i >= CQ * N) return;
    int k = i / N, n = i - k * N;
    float v = W[i];
    __nv_bfloat16 hi = __float2bfloat16(v);
    __nv_bfloat16 lo = __float2bfloat16(v - __bfloat162float(hi));
    dst[(long)k * N + n] = hi;
    dst[(long)(1024 + k) * N + n] = lo;
    dst[(long)(2048 + k) * N + n] = hi;
}

// ---------------------------------------------------------------------------
// bf16 tensor-core GEMM: C[M,N] = g_A3[M,K3] @ B3[K3,N] + bias[N]
// Block tile 128x128, K chunk 32, 256 threads = 8 warps (2 m x 4 n),
// warp tile 64x32, mma.sync m16n8k16, fp32 accumulate.
// MODE 1: B = g_B3, N=3072, scatter outputs into g_q/g_k/g_v as [B,H,T,D]
// MODE 2: B = g_B3p, N=1024, plain write to C
// ---------------------------------------------------------------------------
template<int MODE>
__global__ __launch_bounds__(256)
void gemm_bf16(const float* __restrict__ bias, float* __restrict__ C)
{
    const int N = (MODE == 1) ? 3072 : 1024;
    const __nv_bfloat16* A = g_A3;
    const __nv_bfloat16* B = (MODE == 1) ? g_B3 : g_B3p;

    __shared__ __nv_bfloat16 As[128][40];    // padded: 80B stride
    __shared__ __nv_bfloat16 Bs[32][136];    // padded: 272B stride

    int tid = threadIdx.x;
    int lane = tid & 31;
    int w = tid >> 5;
    int wm = (w & 1) * 64;          // warp m offset in tile
    int wn = (w >> 1) * 32;         // warp n offset in tile
    int m0 = blockIdx.y * 128;
    int n0 = blockIdx.x * 128;

    float acc[4][4][4];
    #pragma unroll
    for (int i = 0; i < 4; i++)
        #pragma unroll
        for (int j = 0; j < 4; j++)
            #pragma unroll
            for (int f = 0; f < 4; f++) acc[i][j][f] = 0.f;

    for (int k0 = 0; k0 < K3; k0 += 32) {
        // load A chunk 128x32 and B chunk 32x128 (16B per thread per pass)
        #pragma unroll
        for (int p = 0; p < 2; p++) {
            int u = tid + p * 256;
            int ar = u >> 2, ac = (u & 3) * 8;
            *(float4*)&As[ar][ac] = *(const float4*)&A[(long)(m0 + ar) * K3 + k0 + ac];
            int br = u >> 4, bc = (u & 15) * 8;
            *(float4*)&Bs[br][bc] = *(const float4*)&B[(long)(k0 + br) * N + n0 + bc];
        }
        __syncthreads();

        #pragma unroll
        for (int kk = 0; kk < 2; kk++) {
            int kb = kk * 16;
            uint32_t a[4][4], b[2][4];
            #pragma unroll
            for (int mi = 0; mi < 4; mi++) {
                uint32_t addr = (uint32_t)__cvta_generic_to_shared(
                    &As[wm + mi * 16 + (lane & 15)][kb + (lane >> 4) * 8]);
                asm volatile("ldmatrix.sync.aligned.m8n8.x4.shared.b16 {%0,%1,%2,%3},[%4];"
                             : "=r"(a[mi][0]), "=r"(a[mi][1]), "=r"(a[mi][2]), "=r"(a[mi][3])
                             : "r"(addr));
            }
            #pragma unroll
            for (int nj = 0; nj < 2; nj++) {
                uint32_t addr = (uint32_t)__cvta_generic_to_shared(
                    &Bs[kb + (lane & 15)][wn + nj * 16 + (lane >> 4) * 8]);
                asm volatile("ldmatrix.sync.aligned.m8n8.x4.trans.shared.b16 {%0,%1,%2,%3},[%4];"
                             : "=r"(b[nj][0]), "=r"(b[nj][1]), "=r"(b[nj][2]), "=r"(b[nj][3])
                             : "r"(addr));
            }
            #pragma unroll
            for (int mi = 0; mi < 4; mi++)
                #pragma unroll
                for (int ni = 0; ni < 4; ni++) {
                    uint32_t b0 = b[ni >> 1][(ni & 1) * 2 + 0];
                    uint32_t b1 = b[ni >> 1][(ni & 1) * 2 + 1];
                    float* d = acc[mi][ni];
                    asm volatile(
                        "mma.sync.aligned.m16n8k16.row.col.f32.bf16.bf16.f32 "
                        "{%0,%1,%2,%3},{%4,%5,%6,%7},{%8,%9},{%0,%1,%2,%3};"
                        : "+f"(d[0]), "+f"(d[1]), "+f"(d[2]), "+f"(d[3])
                        : "r"(a[mi][0]), "r"(a[mi][1]), "r"(a[mi][2]), "r"(a[mi][3]),
                          "r"(b0), "r"(b1));
                }
        }
        __syncthreads();
    }

    // epilogue
    #pragma unroll
    for (int mi = 0; mi < 4; mi++)
        #pragma unroll
        for (int ni = 0; ni < 4; ni++)
            #pragma unroll
            for (int f = 0; f < 4; f++) {
                int m = m0 + wm + mi * 16 + (lane >> 2) + (f >> 1) * 8;
                int n = n0 + wn + ni * 8 + (lane & 3) * 2 + (f & 1);
                float v = acc[mi][ni][f] + bias[n];
                if (MODE == 1) {
                    int which = n >> 10;        // 0=q 1=k 2=v
                    int cc = n & 1023;
                    int h = cc >> 6;
                    int d = cc & 63;
                    int bb = m >> 11;           // T = 2048
                    int t = m & 2047;
                    float* dst = (which == 0) ? g_q : ((which == 1) ? g_k : g_v);
                    dst[(((bb << 4) + h) * (long)TQ + t) * DQ + d] = v;
                } else {
                    C[(long)m * N + n] = v;
                }
            }
}

// ---------------------------------------------------------------------------
// RoPE in-place on g_q, g_k. One thread per (bh,t) row per dim-pair.
// ---------------------------------------------------------------------------
__global__ void rope_kernel()
{
    int idx = blockIdx.x * blockDim.x + threadIdx.x;
    int lane = idx & 31;            // dim pair index j (dims j and j+32)
    int row = idx >> 5;             // bh*T + t
    if (row >= BH * TQ) return;
    int t = row & (TQ - 1);

    float inv_freq = 1.0f / powf(10000.0f, (float)(2 * lane) / 64.0f);
    float ang = (float)t * inv_freq;
    float c = cosf(ang);
    float s = sinf(ang);

    float* qp = g_q + (long)row * DQ;
    float q0 = qp[lane], q1 = qp[lane + 32];
    qp[lane]      = q0 * c - q1 * s;
    qp[lane + 32] = q1 * c + q0 * s;

    float* kp = g_k + (long)row * DQ;
    float k0 = kp[lane], k1 = kp[lane + 32];
    kp[lane]      = k0 * c - k1 * s;
    kp[lane + 32] = k1 * c + k0 * s;
}

// ---------------------------------------------------------------------------
// Flash attention fp32. grid = (BH, T/32). 256 threads = 8 warps.
// Each warp owns 4 query rows; block iterates 32-key chunks (causal).
// Output y laid out [B, T, H*D] (= [4096, 1024]) for the proj GEMM.
// ---------------------------------------------------------------------------
__global__ __launch_bounds__(256)
void flash_attn()
{
    __shared__ float Qs[32][64];
    __shared__ float Ks[32][68];
    __shared__ float Vs[32][68];
    __shared__ float Ps[8][4][33];

    int bh = blockIdx.x;
    int r0 = blockIdx.y * 32;
    int tid = threadIdx.x;
    int w = tid >> 5;
    int lane = tid & 31;
    int row_in = w * 4;

    const float* qb = g_q + (long)bh * TQ * DQ;
    const float* kb = g_k + (long)bh * TQ * DQ;
    const float* vb = g_v + (long)bh * TQ * DQ;

    for (int i = tid; i < 32 * 64; i += 256)
        Qs[i >> 6][i & 63] = qb[(long)(r0 + (i >> 6)) * DQ + (i & 63)];

    float mx[4], l[4], acc0[4], acc1[4];
    #pragma unroll
    for (int i = 0; i < 4; i++) { mx[i] = -1e30f; l[i] = 0.f; acc0[i] = 0.f; acc1[i] = 0.f; }

    int nch = blockIdx.y + 1;
    for (int c2 = 0; c2 < nch; c2++) {
        int kb0 = c2 * 32;
        __syncthreads();
        for (int i = tid; i < 32 * 64; i += 256) {
            int r = i >> 6, d = i & 63;
            Ks[r][d] = kb[(long)(kb0 + r) * DQ + d];
            Vs[r][d] = vb[(long)(kb0 + r) * DQ + d];
        }
        __syncthreads();

        float s[4] = {0.f, 0.f, 0.f, 0.f};
        #pragma unroll
        for (int d4 = 0; d4 < 16; d4++) {
            float4 kv = *(const float4*)&Ks[lane][d4 * 4];
            #pragma unroll
            for (int i = 0; i < 4; i++) {
                float4 qv = *(const float4*)&Qs[row_in + i][d4 * 4];
                s[i] += qv.x * kv.x + qv.y * kv.y + qv.z * kv.z + qv.w * kv.w;
            }
        }

        __syncwarp();
        #pragma unroll
        for (int i = 0; i < 4; i++) {
            int row = r0 + row_in + i;
            float sv = (kb0 + lane > row) ? -1e30f : s[i] * 0.125f;
            float m2 = sv;
            #pragma unroll
            for (int off = 16; off; off >>= 1)
                m2 = fmaxf(m2, __shfl_xor_sync(0xffffffffu, m2, off));
            float mnew = fmaxf(mx[i], m2);
            float scale = __expf(mx[i] - mnew);
            float p = __expf(sv - mnew);
            float ps = p;
            #pragma unroll
            for (int off = 16; off; off >>= 1)
                ps += __shfl_xor_sync(0xffffffffu, ps, off);
            l[i] = l[i] * scale + ps;
            acc0[i] *= scale;
            acc1[i] *= scale;
            mx[i] = mnew;
            Ps[w][i][lane] = p;
        }
        __syncwarp();

        #pragma unroll
        for (int j = 0; j < 32; j++) {
            float v0 = Vs[j][lane];
            float v1 = Vs[j][lane + 32];
            #pragma unroll
            for (int i = 0; i < 4; i++) {
                float pj = Ps[w][i][j];
                acc0[i] = fmaf(pj, v0, acc0[i]);
                acc1[i] = fmaf(pj, v1, acc1[i]);
            }
        }
        __syncwarp();
    }

    int b = bh >> 4, h = bh & 15;
    #pragma unroll
    for (int i = 0; i < 4; i++) {
        int t = r0 + row_in + i;
        float inv = 1.0f / l[i];
        float* yp = g_y + ((long)(b * TQ + t) * CQ) + h * 64;
        yp[lane]      = acc0[i] * inv;
        yp[lane + 32] = acc1[i] * inv;
    }
}

// ---------------------------------------------------------------------------
extern "C" void kernel_launch(void* const* d_in, const int* in_sizes, int n_in,
                              void* d_out, int out_size)
{
    const float* x     = (const float*)d_in[0];
    const float* Wqkv  = (const float*)d_in[1];
    const float* bqkv  = (const float*)d_in[2];
    const float* Wproj = (const float*)d_in[3];
    const float* bproj = (const float*)d_in[4];
    float* out = (float*)d_out;

    // --- QKV: split-convert, bf16 MMA GEMM, scatter to [B,H,T,D] ---
    conv_A3<0><<<(M_ROWS * CQ) / 256, 256>>>(x);
    conv_B3<0><<<(CQ * 3072) / 256, 256>>>(Wqkv);
    gemm_bf16<1><<<dim3(3072 / 128, M_ROWS / 128), 256>>>(bqkv, nullptr);

    // --- RoPE + causal flash attention -> g_y [B,T,C] ---
    rope_kernel<<<(BH * TQ * 32) / 256, 256>>>();
    flash_attn<<<dim3(BH, TQ / 32), 256>>>();

    // --- Proj: split-convert y, bf16 MMA GEMM ---
    conv_A3<1><<<(M_ROWS * CQ) / 256, 256>>>(nullptr);
    conv_B3<1><<<(CQ * 1024) / 256, 256>>>(Wproj);
    gemm_bf16<2><<<dim3(1024 / 128, M_ROWS / 128), 256>>>(bproj, out);
}

// round 6
// speedup vs baseline: 3.2077x; 2.2502x over previous
#include <cuda_runtime.h>
#include <cuda_bf16.h>
#include <cuda_fp16.h>
#include <stdint.h>
#include <math.h>

#define BQ 2
#define TQ 2048
#define CQ 1024
#define HQ 16
#define DQ 64
#define BH (BQ*HQ)
#define M_ROWS (BQ*TQ)          // 4096
#define K3 3072                 // tripled K for hi/lo split GEMM

// Scratch (allocation-free rule: static device globals)
__device__ float g_q[BQ*HQ*TQ*DQ];
__device__ float g_k[BQ*HQ*TQ*DQ];
__device__ float g_v[BQ*HQ*TQ*DQ];
__device__ float g_y[BQ*TQ*CQ];
__device__ __half g_qh[BQ*HQ*TQ*DQ];    // fp16 q, pre-scaled by 1/8
__device__ __half g_kT[BQ*HQ*DQ*TQ];    // fp16 k transposed [bh][d][t]
__device__ __half g_vh[BQ*HQ*TQ*DQ];    // fp16 v
__device__ __nv_bfloat16 g_A3[(long)M_ROWS * K3];     // [4096, 3072]
__device__ __nv_bfloat16 g_B3[(long)K3 * 3072];       // qkv weights split
__device__ __nv_bfloat16 g_B3p[(long)K3 * 1024];      // proj weights split

// ---------------------------------------------------------------------------
// fp32 -> (hi, lo) bf16 split conversions.
// ---------------------------------------------------------------------------
template<int SRC_Y>
__global__ void conv_A3(const float* __restrict__ src)
{
    int i = blockIdx.x * blockDim.x + threadIdx.x;
    if (i >= M_ROWS * CQ) return;
    const float* s = SRC_Y ? (const float*)g_y : src;
    int m = i >> 10, k = i & 1023;
    float v = s[i];
    __nv_bfloat16 hi = __float2bfloat16(v);
    __nv_bfloat16 lo = __float2bfloat16(v - __bfloat162float(hi));
    long base = (long)m * K3;
    g_A3[base + k] = hi;
    g_A3[base + 1024 + k] = hi;
    g_A3[base + 2048 + k] = lo;
}

template<int WHICH>
__global__ void conv_B3(const float* __restrict__ W)
{
    const int N = WHICH ? 1024 : 3072;
    __nv_bfloat16* dst = WHICH ? g_B3p : g_B3;
    int i = blockIdx.x * blockDim.x + threadIdx.x;
    if (i >= CQ * N) return;
    int k = i / N, n = i - k * N;
    float v = W[i];
    __nv_bfloat16 hi = __float2bfloat16(v);
    __nv_bfloat16 lo = __float2bfloat16(v - __bfloat162float(hi));
    dst[(long)k * N + n] = hi;
    dst[(long)(1024 + k) * N + n] = lo;
    dst[(long)(2048 + k) * N + n] = hi;
}

// ---------------------------------------------------------------------------
// bf16 tensor-core GEMM (unchanged from passing R4 kernel)
// ---------------------------------------------------------------------------
template<int MODE>
__global__ __launch_bounds__(256)
void gemm_bf16(const float* __restrict__ bias, float* __restrict__ C)
{
    const int N = (MODE == 1) ? 3072 : 1024;
    const __nv_bfloat16* A = g_A3;
    const __nv_bfloat16* B = (MODE == 1) ? g_B3 : g_B3p;

    __shared__ __nv_bfloat16 As[128][40];
    __shared__ __nv_bfloat16 Bs[32][136];

    int tid = threadIdx.x;
    int lane = tid & 31;
    int w = tid >> 5;
    int wm = (w & 1) * 64;
    int wn = (w >> 1) * 32;
    int m0 = blockIdx.y * 128;
    int n0 = blockIdx.x * 128;

    float acc[4][4][4];
    #pragma unroll
    for (int i = 0; i < 4; i++)
        #pragma unroll
        for (int j = 0; j < 4; j++)
            #pragma unroll
            for (int f = 0; f < 4; f++) acc[i][j][f] = 0.f;

    for (int k0 = 0; k0 < K3; k0 += 32) {
        #pragma unroll
        for (int p = 0; p < 2; p++) {
            int u = tid + p * 256;
            int ar = u >> 2, ac = (u & 3) * 8;
            *(float4*)&As[ar][ac] = *(const float4*)&A[(long)(m0 + ar) * K3 + k0 + ac];
            int br = u >> 4, bc = (u & 15) * 8;
            *(float4*)&Bs[br][bc] = *(const float4*)&B[(long)(k0 + br) * N + n0 + bc];
        }
        __syncthreads();

        #pragma unroll
        for (int kk = 0; kk < 2; kk++) {
            int kb = kk * 16;
            uint32_t a[4][4], b[2][4];
            #pragma unroll
            for (int mi = 0; mi < 4; mi++) {
                uint32_t addr = (uint32_t)__cvta_generic_to_shared(
                    &As[wm + mi * 16 + (lane & 15)][kb + (lane >> 4) * 8]);
                asm volatile("ldmatrix.sync.aligned.m8n8.x4.shared.b16 {%0,%1,%2,%3},[%4];"
                             : "=r"(a[mi][0]), "=r"(a[mi][1]), "=r"(a[mi][2]), "=r"(a[mi][3])
                             : "r"(addr));
            }
            #pragma unroll
            for (int nj = 0; nj < 2; nj++) {
                uint32_t addr = (uint32_t)__cvta_generic_to_shared(
                    &Bs[kb + (lane & 15)][wn + nj * 16 + (lane >> 4) * 8]);
                asm volatile("ldmatrix.sync.aligned.m8n8.x4.trans.shared.b16 {%0,%1,%2,%3},[%4];"
                             : "=r"(b[nj][0]), "=r"(b[nj][1]), "=r"(b[nj][2]), "=r"(b[nj][3])
                             : "r"(addr));
            }
            #pragma unroll
            for (int mi = 0; mi < 4; mi++)
                #pragma unroll
                for (int ni = 0; ni < 4; ni++) {
                    uint32_t b0 = b[ni >> 1][(ni & 1) * 2 + 0];
                    uint32_t b1 = b[ni >> 1][(ni & 1) * 2 + 1];
                    float* d = acc[mi][ni];
                    asm volatile(
                        "mma.sync.aligned.m16n8k16.row.col.f32.bf16.bf16.f32 "
                        "{%0,%1,%2,%3},{%4,%5,%6,%7},{%8,%9},{%0,%1,%2,%3};"
                        : "+f"(d[0]), "+f"(d[1]), "+f"(d[2]), "+f"(d[3])
                        : "r"(a[mi][0]), "r"(a[mi][1]), "r"(a[mi][2]), "r"(a[mi][3]),
                          "r"(b0), "r"(b1));
                }
        }
        __syncthreads();
    }

    #pragma unroll
    for (int mi = 0; mi < 4; mi++)
        #pragma unroll
        for (int ni = 0; ni < 4; ni++)
            #pragma unroll
            for (int f = 0; f < 4; f++) {
                int m = m0 + wm + mi * 16 + (lane >> 2) + (f >> 1) * 8;
                int n = n0 + wn + ni * 8 + (lane & 3) * 2 + (f & 1);
                float v = acc[mi][ni][f] + bias[n];
                if (MODE == 1) {
                    int which = n >> 10;
                    int cc = n & 1023;
                    int h = cc >> 6;
                    int d = cc & 63;
                    int bb = m >> 11;
                    int t = m & 2047;
                    float* dst = (which == 0) ? g_q : ((which == 1) ? g_k : g_v);
                    dst[(((bb << 4) + h) * (long)TQ + t) * DQ + d] = v;
                } else {
                    C[(long)m * N + n] = v;
                }
            }
}

// ---------------------------------------------------------------------------
// RoPE: read fp32 q/k, write fp16 q (pre-scaled 1/8), fp16 k transposed
// [bh][d][t], and convert v to fp16.
// ---------------------------------------------------------------------------
__global__ void rope_kernel()
{
    int idx = blockIdx.x * blockDim.x + threadIdx.x;
    int lane = idx & 31;            // dim pair index j (dims j and j+32)
    int row = idx >> 5;             // bh*T + t
    if (row >= BH * TQ) return;
    int t = row & (TQ - 1);
    int bh = row >> 11;

    float inv_freq = 1.0f / powf(10000.0f, (float)(2 * lane) / 64.0f);
    float ang = (float)t * inv_freq;
    float c = cosf(ang);
    float s = sinf(ang);

    const float* qp = g_q + (long)row * DQ;
    float q0 = qp[lane], q1 = qp[lane + 32];
    float qr0 = q0 * c - q1 * s;
    float qr1 = q1 * c + q0 * s;
    g_qh[(long)row * DQ + lane]      = __float2half(qr0 * 0.125f);
    g_qh[(long)row * DQ + lane + 32] = __float2half(qr1 * 0.125f);

    const float* kp = g_k + (long)row * DQ;
    float k0 = kp[lane], k1 = kp[lane + 32];
    float kr0 = k0 * c - k1 * s;
    float kr1 = k1 * c + k0 * s;
    long ktb = (long)bh * DQ * TQ;
    g_kT[ktb + (long)lane * TQ + t]        = __float2half(kr0);
    g_kT[ktb + (long)(lane + 32) * TQ + t] = __float2half(kr1);

    const float* vp = g_v + (long)row * DQ;
    g_vh[(long)row * DQ + lane]      = __float2half(vp[lane]);
    g_vh[(long)row * DQ + lane + 32] = __float2half(vp[lane + 32]);
}

// ---------------------------------------------------------------------------
// fp16 tensor-core flash attention.
// grid = (BH, T/64), 128 threads = 4 warps; warp w owns q rows [w*16, w*16+16)
// of the 64-row tile. Key chunks of 64, causal. Output -> g_y [B,T,H*D] fp32.
// ---------------------------------------------------------------------------
__global__ __launch_bounds__(128)
void flash_attn_h()
{
    __shared__ __half Qs[64][72];    // [q][d], +8 pad
    __shared__ __half Ks[64][72];    // [d][key]
    __shared__ __half Vs[64][72];    // [key][d]

    int bh = blockIdx.x;
    int y  = gridDim.y - 1 - blockIdx.y;   // heavy tiles first
    int tid = threadIdx.x;
    int w = tid >> 5;
    int lane = tid & 31;

    const __half* qb = g_qh + (long)bh * TQ * DQ;
    const __half* kT = g_kT + (long)bh * DQ * TQ;
    const __half* vb = g_vh + (long)bh * TQ * DQ;

    // load Q tile (64 rows x 64 halves)
    #pragma unroll
    for (int p = 0; p < 4; p++) {
        int idx = tid + p * 128;
        int r = idx >> 3, c = (idx & 7) * 8;
        *(float4*)&Qs[r][c] = *(const float4*)&qb[(long)(y * 64 + r) * DQ + c];
    }
    __syncthreads();

    // Q fragments, kept in registers for the whole kv loop
    uint32_t qf[4][4];
    #pragma unroll
    for (int t = 0; t < 4; t++) {
        uint32_t addr = (uint32_t)__cvta_generic_to_shared(
            &Qs[w * 16 + (lane & 15)][t * 16 + (lane >> 4) * 8]);
        asm volatile("ldmatrix.sync.aligned.m8n8.x4.shared.b16 {%0,%1,%2,%3},[%4];"
                     : "=r"(qf[t][0]), "=r"(qf[t][1]), "=r"(qf[t][2]), "=r"(qf[t][3])
                     : "r"(addr));
    }

    float o[8][4];
    #pragma unroll
    for (int i = 0; i < 8; i++)
        #pragma unroll
        for (int f = 0; f < 4; f++) o[i][f] = 0.f;
    float m0 = -1e30f, m1 = -1e30f, l0 = 0.f, l1 = 0.f;

    for (int kc = 0; kc <= y; kc++) {
        __syncthreads();
        #pragma unroll
        for (int p = 0; p < 4; p++) {
            int idx = tid + p * 128;
            int r = idx >> 3, c = (idx & 7) * 8;
            *(float4*)&Ks[r][c] = *(const float4*)&kT[(long)r * TQ + kc * 64 + c];
            *(float4*)&Vs[r][c] = *(const float4*)&vb[(long)(kc * 64 + r) * DQ + c];
        }
        __syncthreads();

        // S = Q @ K^T : 8 n-tiles of 8 keys
        float s[8][4];
        #pragma unroll
        for (int i = 0; i < 8; i++)
            #pragma unroll
            for (int f = 0; f < 4; f++) s[i][f] = 0.f;

        #pragma unroll
        for (int t = 0; t < 4; t++) {
            uint32_t kb[4][4];
            #pragma unroll
            for (int nj = 0; nj < 4; nj++) {
                uint32_t addr = (uint32_t)__cvta_generic_to_shared(
                    &Ks[t * 16 + (lane & 15)][nj * 16 + (lane >> 4) * 8]);
                asm volatile("ldmatrix.sync.aligned.m8n8.x4.trans.shared.b16 {%0,%1,%2,%3},[%4];"
                             : "=r"(kb[nj][0]), "=r"(kb[nj][1]), "=r"(kb[nj][2]), "=r"(kb[nj][3])
                             : "r"(addr));
            }
            #pragma unroll
            for (int ni = 0; ni < 8; ni++) {
                uint32_t b0 = kb[ni >> 1][(ni & 1) * 2 + 0];
                uint32_t b1 = kb[ni >> 1][(ni & 1) * 2 + 1];
                asm volatile(
                    "mma.sync.aligned.m16n8k16.row.col.f32.f16.f16.f32 "
                    "{%0,%1,%2,%3},{%4,%5,%6,%7},{%8,%9},{%0,%1,%2,%3};"
                    : "+f"(s[ni][0]), "+f"(s[ni][1]), "+f"(s[ni][2]), "+f"(s[ni][3])
                    : "r"(qf[t][0]), "r"(qf[t][1]), "r"(qf[t][2]), "r"(qf[t][3]),
                      "r"(b0), "r"(b1));
            }
        }

        // causal mask on diagonal chunk
        if (kc == y) {
            int qr0 = y * 64 + w * 16 + (lane >> 2);
            int qr1 = qr0 + 8;
            #pragma unroll
            for (int ni = 0; ni < 8; ni++) {
                int kcol = kc * 64 + ni * 8 + ((lane & 3) << 1);
                if (kcol     > qr0) s[ni][0] = -1e30f;
                if (kcol + 1 > qr0) s[ni][1] = -1e30f;
                if (kcol     > qr1) s[ni][2] = -1e30f;
                if (kcol + 1 > qr1) s[ni][3] = -1e30f;
            }
        }

        // online softmax (rows r = lane>>2 and r+8)
        float mx0 = -1e30f, mx1 = -1e30f;
        #pragma unroll
        for (int ni = 0; ni < 8; ni++) {
            mx0 = fmaxf(mx0, fmaxf(s[ni][0], s[ni][1]));
            mx1 = fmaxf(mx1, fmaxf(s[ni][2], s[ni][3]));
        }
        mx0 = fmaxf(mx0, __shfl_xor_sync(0xffffffffu, mx0, 1));
        mx0 = fmaxf(mx0, __shfl_xor_sync(0xffffffffu, mx0, 2));
        mx1 = fmaxf(mx1, __shfl_xor_sync(0xffffffffu, mx1, 1));
        mx1 = fmaxf(mx1, __shfl_xor_sync(0xffffffffu, mx1, 2));
        float mn0 = fmaxf(m0, mx0), mn1 = fmaxf(m1, mx1);
        float a0 = __expf(m0 - mn0), a1 = __expf(m1 - mn1);
        m0 = mn0; m1 = mn1;

        float ls0 = 0.f, ls1 = 0.f;
        uint32_t pf01[8], pf23[8];
        #pragma unroll
        for (int ni = 0; ni < 8; ni++) {
            float p0 = __expf(s[ni][0] - mn0);
            float p1 = __expf(s[ni][1] - mn0);
            float p2 = __expf(s[ni][2] - mn1);
            float p3 = __expf(s[ni][3] - mn1);
            ls0 += p0 + p1;
            ls1 += p2 + p3;
            __half2 h01 = __floats2half2_rn(p0, p1);
            __half2 h23 = __floats2half2_rn(p2, p3);
            pf01[ni] = *(uint32_t*)&h01;
            pf23[ni] = *(uint32_t*)&h23;
        }
        l0 = l0 * a0 + ls0;
        l1 = l1 * a1 + ls1;
        #pragma unroll
        for (int ni = 0; ni < 8; ni++) {
            o[ni][0] *= a0; o[ni][1] *= a0;
            o[ni][2] *= a1; o[ni][3] *= a1;
        }

        // O += P @ V : k = keys (4 steps), n = d (8 tiles)
        #pragma unroll
        for (int t = 0; t < 4; t++) {
            uint32_t vf[4][4];
            #pragma unroll
            for (int dj = 0; dj < 4; dj++) {
                uint32_t addr = (uint32_t)__cvta_generic_to_shared(
                    &Vs[t * 16 + (lane & 15)][dj * 16 + (lane >> 4) * 8]);
                asm volatile("ldmatrix.sync.aligned.m8n8.x4.trans.shared.b16 {%0,%1,%2,%3},[%4];"
                             : "=r"(vf[dj][0]), "=r"(vf[dj][1]), "=r"(vf[dj][2]), "=r"(vf[dj][3])
                             : "r"(addr));
            }
            uint32_t pa0 = pf01[2 * t], pa1 = pf23[2 * t];
            uint32_t pa2 = pf01[2 * t + 1], pa3 = pf23[2 * t + 1];
            #pragma unroll
            for (int ni = 0; ni < 8; ni++) {
                uint32_t b0 = vf[ni >> 1][(ni & 1) * 2 + 0];
                uint32_t b1 = vf[ni >> 1][(ni & 1) * 2 + 1];
                asm volatile(
                    "mma.sync.aligned.m16n8k16.row.col.f32.f16.f16.f32 "
                    "{%0,%1,%2,%3},{%4,%5,%6,%7},{%8,%9},{%0,%1,%2,%3};"
                    : "+f"(o[ni][0]), "+f"(o[ni][1]), "+f"(o[ni][2]), "+f"(o[ni][3])
                    : "r"(pa0), "r"(pa1), "r"(pa2), "r"(pa3),
                      "r"(b0), "r"(b1));
            }
        }
    }

    // finalize: reduce l over quad, normalize, write
    l0 += __shfl_xor_sync(0xffffffffu, l0, 1);
    l0 += __shfl_xor_sync(0xffffffffu, l0, 2);
    l1 += __shfl_xor_sync(0xffffffffu, l1, 1);
    l1 += __shfl_xor_sync(0xffffffffu, l1, 2);
    float inv0 = 1.0f / l0, inv1 = 1.0f / l1;

    int b = bh >> 4, h = bh & 15;
    int r0 = y * 64 + w * 16 + (lane >> 2);
    #pragma unroll
    for (int ni = 0; ni < 8; ni++) {
        int d = h * 64 + ni * 8 + ((lane & 3) << 1);
        float2 v0 = make_float2(o[ni][0] * inv0, o[ni][1] * inv0);
        float2 v1 = make_float2(o[ni][2] * inv1, o[ni][3] * inv1);
        *(float2*)&g_y[(long)(b * TQ + r0) * CQ + d] = v0;
        *(float2*)&g_y[(long)(b * TQ + r0 + 8) * CQ + d] = v1;
    }
}

// ---------------------------------------------------------------------------
extern "C" void kernel_launch(void* const* d_in, const int* in_sizes, int n_in,
                              void* d_out, int out_size)
{
    const float* x     = (const float*)d_in[0];
    const float* Wqkv  = (const float*)d_in[1];
    const float* bqkv  = (const float*)d_in[2];
    const float* Wproj = (const float*)d_in[3];
    const float* bproj = (const float*)d_in[4];
    float* out = (float*)d_out;

    // --- QKV: split-convert, bf16 MMA GEMM, scatter to [B,H,T,D] ---
    conv_A3<0><<<(M_ROWS * CQ) / 256, 256>>>(x);
    conv_B3<0><<<(CQ * 3072) / 256, 256>>>(Wqkv);
    gemm_bf16<1><<<dim3(3072 / 128, M_ROWS / 128), 256>>>(bqkv, nullptr);

    // --- RoPE (emit fp16 q/kT/v) + fp16 tensor-core flash attention ---
    rope_kernel<<<(BH * TQ * 32) / 256, 256>>>();
    flash_attn_h<<<dim3(BH, TQ / 64), 128>>>();

    // --- Proj: split-convert y, bf16 MMA GEMM ---
    conv_A3<1><<<(M_ROWS * CQ) / 256, 256>>>(nullptr);
    conv_B3<1><<<(CQ * 1024) / 256, 256>>>(Wproj);
    gemm_bf16<2><<<dim3(1024 / 128, M_ROWS / 128), 256>>>(bproj, out);
}

// round 7
// speedup vs baseline: 3.5584x; 1.1093x over previous
#include <cuda_runtime.h>
#include <cuda_bf16.h>
#include <cuda_fp16.h>
#include <stdint.h>
#include <math.h>

#define BQ 2
#define TQ 2048
#define CQ 1024
#define HQ 16
#define DQ 64
#define BH (BQ*HQ)
#define M_ROWS (BQ*TQ)          // 4096
#define K3 3072                 // tripled K for hi/lo split GEMM

// Scratch (allocation-free rule: static device globals)
__device__ float g_q[BQ*HQ*TQ*DQ];
__device__ float g_k[BQ*HQ*TQ*DQ];
__device__ float g_v[BQ*HQ*TQ*DQ];
__device__ float g_y[BQ*TQ*CQ];
__device__ __half g_qh[BQ*HQ*TQ*DQ];    // fp16 q, pre-scaled by 1/8
__device__ __half g_kh[BQ*HQ*TQ*DQ];    // fp16 k (natural [bh][t][d] layout)
__device__ __half g_vh[BQ*HQ*TQ*DQ];    // fp16 v
__device__ __nv_bfloat16 g_A3[(long)M_ROWS * K3];     // [4096, 3072]
__device__ __nv_bfloat16 g_B3[(long)K3 * 3072];       // qkv weights split
__device__ __nv_bfloat16 g_B3p[(long)K3 * 1024];      // proj weights split

// ---------------------------------------------------------------------------
// fp32 -> (hi, lo) bf16 split conversions.
// ---------------------------------------------------------------------------
template<int SRC_Y>
__global__ void conv_A3(const float* __restrict__ src)
{
    int i = blockIdx.x * blockDim.x + threadIdx.x;
    if (i >= M_ROWS * CQ) return;
    const float* s = SRC_Y ? (const float*)g_y : src;
    int m = i >> 10, k = i & 1023;
    float v = s[i];
    __nv_bfloat16 hi = __float2bfloat16(v);
    __nv_bfloat16 lo = __float2bfloat16(v - __bfloat162float(hi));
    long base = (long)m * K3;
    g_A3[base + k] = hi;
    g_A3[base + 1024 + k] = hi;
    g_A3[base + 2048 + k] = lo;
}

template<int WHICH>
__global__ void conv_B3(const float* __restrict__ W)
{
    const int N = WHICH ? 1024 : 3072;
    __nv_bfloat16* dst = WHICH ? g_B3p : g_B3;
    int i = blockIdx.x * blockDim.x + threadIdx.x;
    if (i >= CQ * N) return;
    int k = i / N, n = i - k * N;
    float v = W[i];
    __nv_bfloat16 hi = __float2bfloat16(v);
    __nv_bfloat16 lo = __float2bfloat16(v - __bfloat162float(hi));
    dst[(long)k * N + n] = hi;
    dst[(long)(1024 + k) * N + n] = lo;
    dst[(long)(2048 + k) * N + n] = hi;
}

// ---------------------------------------------------------------------------
// bf16 tensor-core GEMM with cp.async 2-stage pipeline.
// C[M,N] = g_A3[M,K3] @ B3[K3,N] + bias[N]
// Block tile 128x128, BK=32, 256 threads = 8 warps, warp tile 64x32.
// MODE 1: B = g_B3, N=3072, scatter to g_q/g_k/g_v; MODE 2: B = g_B3p, N=1024.
// ---------------------------------------------------------------------------
#define CP_ASYNC16(dst_u32, src_ptr) \
    asm volatile("cp.async.cg.shared.global [%0], [%1], 16;\n" \
                 :: "r"(dst_u32), "l"(src_ptr))
#define CP_COMMIT() asm volatile("cp.async.commit_group;\n")
#define CP_WAIT(n)  asm volatile("cp.async.wait_group %0;\n" :: "n"(n))

template<int MODE>
__global__ __launch_bounds__(256)
void gemm_bf16(const float* __restrict__ bias, float* __restrict__ C)
{
    const int N = (MODE == 1) ? 3072 : 1024;
    const __nv_bfloat16* A = g_A3;
    const __nv_bfloat16* B = (MODE == 1) ? g_B3 : g_B3p;

    __shared__ __nv_bfloat16 As[2][128][40];   // 80B row stride (16B-aligned)
    __shared__ __nv_bfloat16 Bs[2][32][136];   // 272B row stride (16B-aligned)

    int tid = threadIdx.x;
    int lane = tid & 31;
    int w = tid >> 5;
    int wm = (w & 1) * 64;
    int wn = (w >> 1) * 32;
    int m0 = blockIdx.y * 128;
    int n0 = blockIdx.x * 128;

    // per-thread load coords (2 chunks of 16B each for A and B)
    int ar0 = tid >> 1,               ac0 = (tid & 1) * 8;       // u = tid (A pass0: u>>2? see below)
    // A chunk: 128 rows x 32 cols = 512 x 16B; thread does u=tid, tid+256
    // B chunk: 32 rows x 128 cols = 512 x 16B
    float acc[4][4][4];
    #pragma unroll
    for (int i = 0; i < 4; i++)
        #pragma unroll
        for (int j = 0; j < 4; j++)
            #pragma unroll
            for (int f = 0; f < 4; f++) acc[i][j][f] = 0.f;
    (void)ar0; (void)ac0;

    const int NIT = K3 / 32;

    // prefetch stage 0
    {
        int k0 = 0;
        #pragma unroll
        for (int p = 0; p < 2; p++) {
            int u = tid + p * 256;
            int ar = u >> 2, ac = (u & 3) * 8;
            uint32_t d = (uint32_t)__cvta_generic_to_shared(&As[0][ar][ac]);
            CP_ASYNC16(d, &A[(long)(m0 + ar) * K3 + k0 + ac]);
            int br = u >> 4, bc = (u & 15) * 8;
            uint32_t d2 = (uint32_t)__cvta_generic_to_shared(&Bs[0][br][bc]);
            CP_ASYNC16(d2, &B[(long)(k0 + br) * N + n0 + bc]);
        }
        CP_COMMIT();
    }

    for (int it = 0; it < NIT; it++) {
        int s = it & 1;
        if (it + 1 < NIT) {
            int k0 = (it + 1) * 32;
            int sn = s ^ 1;
            #pragma unroll
            for (int p = 0; p < 2; p++) {
                int u = tid + p * 256;
                int ar = u >> 2, ac = (u & 3) * 8;
                uint32_t d = (uint32_t)__cvta_generic_to_shared(&As[sn][ar][ac]);
                CP_ASYNC16(d, &A[(long)(m0 + ar) * K3 + k0 + ac]);
                int br = u >> 4, bc = (u & 15) * 8;
                uint32_t d2 = (uint32_t)__cvta_generic_to_shared(&Bs[sn][br][bc]);
                CP_ASYNC16(d2, &B[(long)(k0 + br) * N + n0 + bc]);
            }
            CP_COMMIT();
            CP_WAIT(1);
        } else {
            CP_WAIT(0);
        }
        __syncthreads();

        #pragma unroll
        for (int kk = 0; kk < 2; kk++) {
            int kb = kk * 16;
            uint32_t a[4][4], b[2][4];
            #pragma unroll
            for (int mi = 0; mi < 4; mi++) {
                uint32_t addr = (uint32_t)__cvta_generic_to_shared(
                    &As[s][wm + mi * 16 + (lane & 15)][kb + (lane >> 4) * 8]);
                asm volatile("ldmatrix.sync.aligned.m8n8.x4.shared.b16 {%0,%1,%2,%3},[%4];"
                             : "=r"(a[mi][0]), "=r"(a[mi][1]), "=r"(a[mi][2]), "=r"(a[mi][3])
                             : "r"(addr));
            }
            #pragma unroll
            for (int nj = 0; nj < 2; nj++) {
                uint32_t addr = (uint32_t)__cvta_generic_to_shared(
                    &Bs[s][kb + (lane & 15)][wn + nj * 16 + (lane >> 4) * 8]);
                asm volatile("ldmatrix.sync.aligned.m8n8.x4.trans.shared.b16 {%0,%1,%2,%3},[%4];"
                             : "=r"(b[nj][0]), "=r"(b[nj][1]), "=r"(b[nj][2]), "=r"(b[nj][3])
                             : "r"(addr));
            }
            #pragma unroll
            for (int mi = 0; mi < 4; mi++)
                #pragma unroll
                for (int ni = 0; ni < 4; ni++) {
                    uint32_t b0 = b[ni >> 1][(ni & 1) * 2 + 0];
                    uint32_t b1 = b[ni >> 1][(ni & 1) * 2 + 1];
                    float* d = acc[mi][ni];
                    asm volatile(
                        "mma.sync.aligned.m16n8k16.row.col.f32.bf16.bf16.f32 "
                        "{%0,%1,%2,%3},{%4,%5,%6,%7},{%8,%9},{%0,%1,%2,%3};"
                        : "+f"(d[0]), "+f"(d[1]), "+f"(d[2]), "+f"(d[3])
                        : "r"(a[mi][0]), "r"(a[mi][1]), "r"(a[mi][2]), "r"(a[mi][3]),
                          "r"(b0), "r"(b1));
                }
        }
        __syncthreads();
    }

    #pragma unroll
    for (int mi = 0; mi < 4; mi++)
        #pragma unroll
        for (int ni = 0; ni < 4; ni++)
            #pragma unroll
            for (int f = 0; f < 4; f++) {
                int m = m0 + wm + mi * 16 + (lane >> 2) + (f >> 1) * 8;
                int n = n0 + wn + ni * 8 + (lane & 3) * 2 + (f & 1);
                float v = acc[mi][ni][f] + bias[n];
                if (MODE == 1) {
                    int which = n >> 10;
                    int cc = n & 1023;
                    int h = cc >> 6;
                    int d = cc & 63;
                    int bb = m >> 11;
                    int t = m & 2047;
                    float* dst = (which == 0) ? g_q : ((which == 1) ? g_k : g_v);
                    dst[(((bb << 4) + h) * (long)TQ + t) * DQ + d] = v;
                } else {
                    C[(long)m * N + n] = v;
                }
            }
}

// ---------------------------------------------------------------------------
// RoPE: read fp32 q/k, write fp16 q (pre-scaled 1/8), fp16 k, fp16 v — all
// in natural coalesced [bh][t][d] layout.
// ---------------------------------------------------------------------------
__global__ void rope_kernel()
{
    int idx = blockIdx.x * blockDim.x + threadIdx.x;
    int lane = idx & 31;            // dim pair index j (dims j and j+32)
    int row = idx >> 5;             // bh*T + t
    if (row >= BH * TQ) return;
    int t = row & (TQ - 1);

    float inv_freq = 1.0f / powf(10000.0f, (float)(2 * lane) / 64.0f);
    float ang = (float)t * inv_freq;
    float c = cosf(ang);
    float s = sinf(ang);

    const float* qp = g_q + (long)row * DQ;
    float q0 = qp[lane], q1 = qp[lane + 32];
    g_qh[(long)row * DQ + lane]      = __float2half((q0 * c - q1 * s) * 0.125f);
    g_qh[(long)row * DQ + lane + 32] = __float2half((q1 * c + q0 * s) * 0.125f);

    const float* kp = g_k + (long)row * DQ;
    float k0 = kp[lane], k1 = kp[lane + 32];
    g_kh[(long)row * DQ + lane]      = __float2half(k0 * c - k1 * s);
    g_kh[(long)row * DQ + lane + 32] = __float2half(k1 * c + k0 * s);

    const float* vp = g_v + (long)row * DQ;
    g_vh[(long)row * DQ + lane]      = __float2half(vp[lane]);
    g_vh[(long)row * DQ + lane + 32] = __float2half(vp[lane + 32]);
}

// ---------------------------------------------------------------------------
// fp16 tensor-core flash attention.
// grid = (BH, T/64), 128 threads = 4 warps; warp w owns q rows [w*16, w*16+16).
// K stored [key][d]; K fragments via NON-trans ldmatrix (B-frag of row.col).
// ---------------------------------------------------------------------------
__global__ __launch_bounds__(128)
void flash_attn_h()
{
    __shared__ __half Qs[64][72];    // [q][d], +8 pad
    __shared__ __half Ks[64][72];    // [key][d]
    __shared__ __half Vs[64][72];    // [key][d]

    int bh = blockIdx.x;
    int y  = gridDim.y - 1 - blockIdx.y;   // heavy tiles first
    int tid = threadIdx.x;
    int w = tid >> 5;
    int lane = tid & 31;

    const __half* qb = g_qh + (long)bh * TQ * DQ;
    const __half* kb = g_kh + (long)bh * TQ * DQ;
    const __half* vb = g_vh + (long)bh * TQ * DQ;

    #pragma unroll
    for (int p = 0; p < 4; p++) {
        int idx = tid + p * 128;
        int r = idx >> 3, c = (idx & 7) * 8;
        *(float4*)&Qs[r][c] = *(const float4*)&qb[(long)(y * 64 + r) * DQ + c];
    }
    __syncthreads();

    uint32_t qf[4][4];
    #pragma unroll
    for (int t = 0; t < 4; t++) {
        uint32_t addr = (uint32_t)__cvta_generic_to_shared(
            &Qs[w * 16 + (lane & 15)][t * 16 + (lane >> 4) * 8]);
        asm volatile("ldmatrix.sync.aligned.m8n8.x4.shared.b16 {%0,%1,%2,%3},[%4];"
                     : "=r"(qf[t][0]), "=r"(qf[t][1]), "=r"(qf[t][2]), "=r"(qf[t][3])
                     : "r"(addr));
    }

    float o[8][4];
    #pragma unroll
    for (int i = 0; i < 8; i++)
        #pragma unroll
        for (int f = 0; f < 4; f++) o[i][f] = 0.f;
    float m0 = -1e30f, m1 = -1e30f, l0 = 0.f, l1 = 0.f;

    for (int kc = 0; kc <= y; kc++) {
        __syncthreads();
        #pragma unroll
        for (int p = 0; p < 4; p++) {
            int idx = tid + p * 128;
            int r = idx >> 3, c = (idx & 7) * 8;
            *(float4*)&Ks[r][c] = *(const float4*)&kb[(long)(kc * 64 + r) * DQ + c];
            *(float4*)&Vs[r][c] = *(const float4*)&vb[(long)(kc * 64 + r) * DQ + c];
        }
        __syncthreads();

        // S = Q @ K^T : K frags via non-trans ldmatrix over [key][d]
        float s[8][4];
        #pragma unroll
        for (int i = 0; i < 8; i++)
            #pragma unroll
            for (int f = 0; f < 4; f++) s[i][f] = 0.f;

        #pragma unroll
        for (int t = 0; t < 4; t++) {
            #pragma unroll
            for (int kj = 0; kj < 4; kj++) {     // 16 keys per x4 load
                uint32_t r[4];
                uint32_t addr = (uint32_t)__cvta_generic_to_shared(
                    &Ks[kj * 16 + (lane & 15)][t * 16 + (lane >> 4) * 8]);
                asm volatile("ldmatrix.sync.aligned.m8n8.x4.shared.b16 {%0,%1,%2,%3},[%4];"
                             : "=r"(r[0]), "=r"(r[1]), "=r"(r[2]), "=r"(r[3])
                             : "r"(addr));
                // keys kj*16..+7 -> regs (r0,r2); keys +8..+15 -> (r1,r3)
                asm volatile(
                    "mma.sync.aligned.m16n8k16.row.col.f32.f16.f16.f32 "
                    "{%0,%1,%2,%3},{%4,%5,%6,%7},{%8,%9},{%0,%1,%2,%3};"
                    : "+f"(s[2*kj][0]), "+f"(s[2*kj][1]), "+f"(s[2*kj][2]), "+f"(s[2*kj][3])
                    : "r"(qf[t][0]), "r"(qf[t][1]), "r"(qf[t][2]), "r"(qf[t][3]),
                      "r"(r[0]), "r"(r[2]));
                asm volatile(
                    "mma.sync.aligned.m16n8k16.row.col.f32.f16.f16.f32 "
                    "{%0,%1,%2,%3},{%4,%5,%6,%7},{%8,%9},{%0,%1,%2,%3};"
                    : "+f"(s[2*kj+1][0]), "+f"(s[2*kj+1][1]), "+f"(s[2*kj+1][2]), "+f"(s[2*kj+1][3])
                    : "r"(qf[t][0]), "r"(qf[t][1]), "r"(qf[t][2]), "r"(qf[t][3]),
                      "r"(r[1]), "r"(r[3]));
            }
        }

        // causal mask on diagonal chunk
        if (kc == y) {
            int qr0 = y * 64 + w * 16 + (lane >> 2);
            int qr1 = qr0 + 8;
            #pragma unroll
            for (int ni = 0; ni < 8; ni++) {
                int kcol = kc * 64 + ni * 8 + ((lane & 3) << 1);
                if (kcol     > qr0) s[ni][0] = -1e30f;
                if (kcol + 1 > qr0) s[ni][1] = -1e30f;
                if (kcol     > qr1) s[ni][2] = -1e30f;
                if (kcol + 1 > qr1) s[ni][3] = -1e30f;
            }
        }

        // online softmax (rows r = lane>>2 and r+8)
        float mx0 = -1e30f, mx1 = -1e30f;
        #pragma unroll
        for (int ni = 0; ni < 8; ni++) {
            mx0 = fmaxf(mx0, fmaxf(s[ni][0], s[ni][1]));
            mx1 = fmaxf(mx1, fmaxf(s[ni][2], s[ni][3]));
        }
        mx0 = fmaxf(mx0, __shfl_xor_sync(0xffffffffu, mx0, 1));
        mx0 = fmaxf(mx0, __shfl_xor_sync(0xffffffffu, mx0, 2));
        mx1 = fmaxf(mx1, __shfl_xor_sync(0xffffffffu, mx1, 1));
        mx1 = fmaxf(mx1, __shfl_xor_sync(0xffffffffu, mx1, 2));
        float mn0 = fmaxf(m0, mx0), mn1 = fmaxf(m1, mx1);
        float a0 = __expf(m0 - mn0), a1 = __expf(m1 - mn1);
        m0 = mn0; m1 = mn1;

        float ls0 = 0.f, ls1 = 0.f;
        uint32_t pf01[8], pf23[8];
        #pragma unroll
        for (int ni = 0; ni < 8; ni++) {
            float p0 = __expf(s[ni][0] - mn0);
            float p1 = __expf(s[ni][1] - mn0);
            float p2 = __expf(s[ni][2] - mn1);
            float p3 = __expf(s[ni][3] - mn1);
            ls0 += p0 + p1;
            ls1 += p2 + p3;
            __half2 h01 = __floats2half2_rn(p0, p1);
            __half2 h23 = __floats2half2_rn(p2, p3);
            pf01[ni] = *(uint32_t*)&h01;
            pf23[ni] = *(uint32_t*)&h23;
        }
        l0 = l0 * a0 + ls0;
        l1 = l1 * a1 + ls1;
        #pragma unroll
        for (int ni = 0; ni < 8; ni++) {
            o[ni][0] *= a0; o[ni][1] *= a0;
            o[ni][2] *= a1; o[ni][3] *= a1;
        }

        // O += P @ V (V is [key][d] = [k][n] -> trans ldmatrix)
        #pragma unroll
        for (int t = 0; t < 4; t++) {
            uint32_t vf[4][4];
            #pragma unroll
            for (int dj = 0; dj < 4; dj++) {
                uint32_t addr = (uint32_t)__cvta_generic_to_shared(
                    &Vs[t * 16 + (lane & 15)][dj * 16 + (lane >> 4) * 8]);
                asm volatile("ldmatrix.sync.aligned.m8n8.x4.trans.shared.b16 {%0,%1,%2,%3},[%4];"
                             : "=r"(vf[dj][0]), "=r"(vf[dj][1]), "=r"(vf[dj][2]), "=r"(vf[dj][3])
                             : "r"(addr));
            }
            uint32_t pa0 = pf01[2 * t], pa1 = pf23[2 * t];
            uint32_t pa2 = pf01[2 * t + 1], pa3 = pf23[2 * t + 1];
            #pragma unroll
            for (int ni = 0; ni < 8; ni++) {
                uint32_t b0 = vf[ni >> 1][(ni & 1) * 2 + 0];
                uint32_t b1 = vf[ni >> 1][(ni & 1) * 2 + 1];
                asm volatile(
                    "mma.sync.aligned.m16n8k16.row.col.f32.f16.f16.f32 "
                    "{%0,%1,%2,%3},{%4,%5,%6,%7},{%8,%9},{%0,%1,%2,%3};"
                    : "+f"(o[ni][0]), "+f"(o[ni][1]), "+f"(o[ni][2]), "+f"(o[ni][3])
                    : "r"(pa0), "r"(pa1), "r"(pa2), "r"(pa3),
                      "r"(b0), "r"(b1));
            }
        }
    }

    l0 += __shfl_xor_sync(0xffffffffu, l0, 1);
    l0 += __shfl_xor_sync(0xffffffffu, l0, 2);
    l1 += __shfl_xor_sync(0xffffffffu, l1, 1);
    l1 += __shfl_xor_sync(0xffffffffu, l1, 2);
    float inv0 = 1.0f / l0, inv1 = 1.0f / l1;

    int b = bh >> 4, h = bh & 15;
    int r0 = y * 64 + w * 16 + (lane >> 2);
    #pragma unroll
    for (int ni = 0; ni < 8; ni++) {
        int d = h * 64 + ni * 8 + ((lane & 3) << 1);
        float2 v0 = make_float2(o[ni][0] * inv0, o[ni][1] * inv0);
        float2 v1 = make_float2(o[ni][2] * inv1, o[ni][3] * inv1);
        *(float2*)&g_y[(long)(b * TQ + r0) * CQ + d] = v0;
        *(float2*)&g_y[(long)(b * TQ + r0 + 8) * CQ + d] = v1;
    }
}

// ---------------------------------------------------------------------------
extern "C" void kernel_launch(void* const* d_in, const int* in_sizes, int n_in,
                              void* d_out, int out_size)
{
    const float* x     = (const float*)d_in[0];
    const float* Wqkv  = (const float*)d_in[1];
    const float* bqkv  = (const float*)d_in[2];
    const float* Wproj = (const float*)d_in[3];
    const float* bproj = (const float*)d_in[4];
    float* out = (float*)d_out;

    conv_A3<0><<<(M_ROWS * CQ) / 256, 256>>>(x);
    conv_B3<0><<<(CQ * 3072) / 256, 256>>>(Wqkv);
    gemm_bf16<1><<<dim3(3072 / 128, M_ROWS / 128), 256>>>(bqkv, nullptr);

    rope_kernel<<<(BH * TQ * 32) / 256, 256>>>();
    flash_attn_h<<<dim3(BH, TQ / 64), 128>>>();

    conv_A3<1><<<(M_ROWS * CQ) / 256, 256>>>(nullptr);
    conv_B3<1><<<(CQ * 1024) / 256, 256>>>(Wproj);
    gemm_bf16<2><<<dim3(1024 / 128, M_ROWS / 128), 256>>>(bproj, out);
}